// round 13
// baseline (speedup 1.0000x reference)
#include <cuda_runtime.h>
#include <cuda_bf16.h>
#include <math.h>

#define BATCH 2
#define HDIM 256
#define WDIM 256
#define CDIM 512
#define KM 64
#define NBLK 8
#define N1 131072          /* WDIM*CDIM */
#define SMEM_MID (1152 * 72 * 2)   /* 165888 B dynamic smem for k_mid */

// ---------------- scratch (device globals; uint4 for 16B alignment) --------
__device__ uint4 g_A1f_4[128 * 128 / 8];            // folded h-DFT
__device__ uint4 g_A2f_4[128 * 256 / 8];            // folded w-DFT
__device__ uint4 g_A4e_4[256 * 64 / 8];             // folded inv-w, even kx
__device__ uint4 g_A4o_4[256 * 64 / 8];             // folded inv-w, odd kx
__device__ uint4 g_A5e_4[128 * 64 / 8];             // folded inv-h, even ky
__device__ uint4 g_A5o_4[128 * 64 / 8];             // folded inv-h, odd ky
__device__ uint4 g_B3_4[8 * 128 * 256 / 8];
__device__ uint4 g_B4_4[8 * 256 * 128 / 8];
__device__ float g_b3f[8 * 256];
__device__ float g_b4f[8 * 128];
__device__ uint4 g_Y_4[(size_t)2 * 128 * N1 / 8];   // [b][ri*64+ky][w*512+c]
__device__ uint4 g_Z_4[(size_t)8192 * 1024 / 8];    // [p][n*128 + ri*64 + c64]
__device__ uint4 g_U_4[(size_t)2 * 128 * N1 / 8];   // [b][ri*64+ky][w*512+c]

#define g_A1f ((__nv_bfloat16*)g_A1f_4)
#define g_A2f ((__nv_bfloat16*)g_A2f_4)
#define g_A4e ((__nv_bfloat16*)g_A4e_4)
#define g_A4o ((__nv_bfloat16*)g_A4o_4)
#define g_A5e ((__nv_bfloat16*)g_A5e_4)
#define g_A5o ((__nv_bfloat16*)g_A5o_4)
#define g_B3  ((__nv_bfloat16*)g_B3_4)
#define g_B4  ((__nv_bfloat16*)g_B4_4)
#define g_Y   ((__nv_bfloat16*)g_Y_4)
#define g_Z   ((__nv_bfloat16*)g_Z_4)
#define g_U   ((__nv_bfloat16*)g_U_4)

// ---------------------------------------------------------------------------
__device__ __forceinline__ float gelu_f(float v) {
    return 0.5f * v * (1.0f + erff(v * 0.70710678118654752440f));
}
__device__ __forceinline__ unsigned pack_bf16(float a, float b) {
    unsigned lo = __bfloat16_as_ushort(__float2bfloat16(a));
    unsigned hi = __bfloat16_as_ushort(__float2bfloat16(b));
    return lo | (hi << 16);
}
__device__ __forceinline__ void mma16816(float* d, const unsigned* a, const unsigned* b) {
    asm volatile(
        "mma.sync.aligned.m16n8k16.row.col.f32.bf16.bf16.f32 "
        "{%0,%1,%2,%3}, {%4,%5,%6,%7}, {%8,%9}, {%0,%1,%2,%3};\n"
        : "+f"(d[0]), "+f"(d[1]), "+f"(d[2]), "+f"(d[3])
        : "r"(a[0]), "r"(a[1]), "r"(a[2]), "r"(a[3]), "r"(b[0]), "r"(b[1]));
}

// ---- cp.async helpers -----------------------------------------------------
__device__ __forceinline__ void cpa16(void* sm, const void* g) {
    unsigned s = (unsigned)__cvta_generic_to_shared(sm);
    asm volatile("cp.async.cg.shared.global [%0], [%1], 16;\n" :: "r"(s), "l"(g));
}
__device__ __forceinline__ void cp_commit() {
    asm volatile("cp.async.commit_group;\n" ::: "memory");
}
__device__ __forceinline__ void cp_wait0() {
    asm volatile("cp.async.wait_group 0;\n" ::: "memory");
}

// ---- tile movers ----------------------------------------------------------
__device__ __forceinline__ void pref_a(const __nv_bfloat16* __restrict__ src,
                                       size_t stride, int tid, uint4* pa) {
    int r = tid >> 1, c0 = (tid & 1) << 5;
    const uint4* p = (const uint4*)(src + (size_t)r * stride + c0);
    pa[0] = p[0]; pa[1] = p[1]; pa[2] = p[2]; pa[3] = p[3];
}
__device__ __forceinline__ void store_a(__nv_bfloat16 (*As)[72], int tid, const uint4* pa) {
    int r = tid >> 1, c0 = (tid & 1) << 5;
    uint4* d = (uint4*)&As[r][c0];
    d[0] = pa[0]; d[1] = pa[1]; d[2] = pa[2]; d[3] = pa[3];
}
__device__ __forceinline__ void cp_a(const __nv_bfloat16* __restrict__ src,
                                     size_t stride, __nv_bfloat16 (*As)[72], int tid) {
    int r = tid >> 1, c0 = (tid & 1) << 5;
    const __nv_bfloat16* g = src + (size_t)r * stride + c0;
#pragma unroll
    for (int j = 0; j < 4; j++) cpa16(&As[r][c0 + j * 8], g + j * 8);
}
__device__ __forceinline__ void cp_b(const __nv_bfloat16* __restrict__ src,
                                     size_t stride, __nv_bfloat16 (*Bs)[72], int tid) {
    int r = tid >> 2, c0 = (tid & 3) << 4;
    const __nv_bfloat16* g = src + (size_t)r * stride + c0;
    cpa16(&Bs[r][c0], g);
    cpa16(&Bs[r][c0 + 8], g + 8);
}
// pair prefetch (rows w and w+off2) for radix-2 folding of bf16 sources
__device__ __forceinline__ void pref_pair(const __nv_bfloat16* __restrict__ src,
                                          size_t stride, size_t off2, int tid, uint4* pb) {
    int r = tid >> 2, c0 = (tid & 3) << 4;
    const uint4* p1 = (const uint4*)(src + (size_t)r * stride + c0);
    const uint4* p2 = (const uint4*)(src + (size_t)r * stride + off2 + c0);
    pb[0] = p1[0]; pb[1] = p1[1]; pb[2] = p2[0]; pb[3] = p2[1];
}
__device__ __forceinline__ void store_sd_b(__nv_bfloat16 (*Bss)[72], __nv_bfloat16 (*Bsd)[72],
                                           int tid, const uint4* pb) {
    int r = tid >> 2, c0 = (tid & 3) << 4;
    const __nv_bfloat162* x1 = (const __nv_bfloat162*)pb;
    const __nv_bfloat162* x2 = (const __nv_bfloat162*)(pb + 2);
    uint4 s[1], d[1];
    __nv_bfloat162* sp = (__nv_bfloat162*)s;
    __nv_bfloat162* dp = (__nv_bfloat162*)d;
#pragma unroll
    for (int h = 0; h < 2; h++) {
#pragma unroll
        for (int j = 0; j < 4; j++) {
            float2 f1 = __bfloat1622float2(x1[h * 4 + j]);
            float2 f2 = __bfloat1622float2(x2[h * 4 + j]);
            sp[j] = __floats2bfloat162_rn(f1.x + f2.x, f1.y + f2.y);
            dp[j] = __floats2bfloat162_rn(f1.x - f2.x, f1.y - f2.y);
        }
        *(uint4*)&Bss[r][c0 + h * 8] = s[0];
        *(uint4*)&Bsd[r][c0 + h * 8] = d[0];
    }
}
// gather-rows cp (even/odd interleave), generic stride
__device__ __forceinline__ void cp_b_gather(const __nv_bfloat16* __restrict__ base,
                                            size_t stride, int koff,
                                            __nv_bfloat16 (*Bs)[72], int tid) {
    int r = tid >> 2, c0 = (tid & 3) << 4;
    int row = (r < 32) ? (2 * r + koff) : (64 + 2 * (r - 32) + koff);
    const __nv_bfloat16* g = base + (size_t)row * stride + c0;
    cpa16(&Bs[r][c0], g);
    cpa16(&Bs[r][c0 + 8], g + 8);
}
// f32 source prefetch (16 floats/thread)
__device__ __forceinline__ void pref_bf(const float* __restrict__ src,
                                        size_t stride, int tid, float4* pf) {
    int r = tid >> 2, c0 = (tid & 3) << 4;
    const float4* p = (const float4*)(src + (size_t)r * stride + c0);
    pf[0] = p[0]; pf[1] = p[1]; pf[2] = p[2]; pf[3] = p[3];
}
__device__ __forceinline__ void store_sd(__nv_bfloat16 (*Bss)[72], __nv_bfloat16 (*Bsd)[72],
                                         int tid, const float4* p1, const float4* p2) {
    int r = tid >> 2, c0 = (tid & 3) << 4;
#pragma unroll
    for (int h = 0; h < 2; h++) {
        float4 a0 = p1[h * 2], a1 = p1[h * 2 + 1];
        float4 b0 = p2[h * 2], b1 = p2[h * 2 + 1];
        uint4 s, d;
        s.x = pack_bf16(a0.x + b0.x, a0.y + b0.y);
        s.y = pack_bf16(a0.z + b0.z, a0.w + b0.w);
        s.z = pack_bf16(a1.x + b1.x, a1.y + b1.y);
        s.w = pack_bf16(a1.z + b1.z, a1.w + b1.w);
        d.x = pack_bf16(a0.x - b0.x, a0.y - b0.y);
        d.y = pack_bf16(a0.z - b0.z, a0.w - b0.w);
        d.z = pack_bf16(a1.x - b1.x, a1.y - b1.y);
        d.w = pack_bf16(a1.z - b1.z, a1.w - b1.w);
        *(uint4*)&Bss[r][c0 + h * 8] = s;
        *(uint4*)&Bsd[r][c0 + h * 8] = d;
    }
}
// core: one 64-deep K tile, block 128x64, 8 warps of 32x32, ldmatrix path
__device__ __forceinline__ void compute_tile(const __nv_bfloat16 (*As)[72],
                                             const __nv_bfloat16 (*Bs)[72],
                                             float acc[2][4][4], int lane, int wm, int wn) {
    const int r8 = lane & 7, q = lane >> 3;
#pragma unroll
    for (int kk = 0; kk < 4; kk++) {
        const int k0 = kk * 16;
        unsigned a[2][4], b[4][2];
#pragma unroll
        for (int fm = 0; fm < 2; fm++) {
            int row = wm * 32 + fm * 16 + (q & 1) * 8 + r8;
            int col = k0 + (q >> 1) * 8;
            unsigned addr = (unsigned)__cvta_generic_to_shared(&As[row][col]);
            asm volatile("ldmatrix.sync.aligned.m8n8.x4.shared.b16 {%0,%1,%2,%3}, [%4];\n"
                         : "=r"(a[fm][0]), "=r"(a[fm][1]), "=r"(a[fm][2]), "=r"(a[fm][3])
                         : "r"(addr));
        }
#pragma unroll
        for (int fn2 = 0; fn2 < 2; fn2++) {
            int krow = k0 + (q & 1) * 8 + r8;
            int ncol = wn * 32 + fn2 * 16 + (q >> 1) * 8;
            unsigned addr = (unsigned)__cvta_generic_to_shared(&Bs[krow][ncol]);
            asm volatile("ldmatrix.sync.aligned.m8n8.x4.trans.shared.b16 {%0,%1,%2,%3}, [%4];\n"
                         : "=r"(b[fn2 * 2][0]), "=r"(b[fn2 * 2][1]),
                           "=r"(b[fn2 * 2 + 1][0]), "=r"(b[fn2 * 2 + 1][1])
                         : "r"(addr));
        }
#pragma unroll
        for (int fm = 0; fm < 2; fm++)
#pragma unroll
            for (int fn = 0; fn < 4; fn++) mma16816(acc[fm][fn], a[fm], b[fn]);
    }
}

// ---------------------------------------------------------------------------
// prep: folded DFT A-matrices
__global__ void k_prep_dft() {
    int id = blockIdx.x * 256 + threadIdx.x;
    const float inv128 = 1.0f / 128.0f;
    if (id < 16384) {                         // A1f [128][128]
        int mp = id >> 7, h = id & 127;
        int par = mp >> 6, ri = (mp >> 5) & 1, ky = 2 * (mp & 31) + par;
        float t = ((ky * h) & 255) * inv128;
        float v = ri ? -sinpif(t) : cospif(t);
        g_A1f[id] = __float2bfloat16(v * 0.0625f);
    } else if (id < 49152) {                  // A2f [128][256]
        int t = id - 16384, mp = t >> 8, k = t & 255;
        int par = mp >> 6, rio = (mp >> 5) & 1, kx = 2 * (mp & 31) + par;
        int rii = k >> 7, w = k & 127;
        float ang = ((kx * w) & 255) * inv128;
        float v = (rio == 0) ? (rii == 0 ? cospif(ang) : sinpif(ang))
                             : (rii == 0 ? -sinpif(ang) : cospif(ang));
        g_A2f[t] = __float2bfloat16(v * 0.0625f);
    } else if (id < 65536) {                  // A4e [256][64]
        int t = id - 49152, mp = t >> 6, k = t & 63;
        int ri = mp >> 7, w = mp & 127;
        int ri2 = k >> 5, kx = 2 * (k & 31);
        float sc = (kx == 0) ? 0.0625f : 0.125f;
        float ang = ((kx * w) & 255) * inv128;
        float v = (ri == 0) ? (ri2 == 0 ? cospif(ang) : -sinpif(ang))
                            : (ri2 == 0 ? sinpif(ang) : cospif(ang));
        g_A4e[t] = __float2bfloat16(v * sc);
    } else if (id < 81920) {                  // A4o [256][64]
        int t = id - 65536, mp = t >> 6, k = t & 63;
        int ri = mp >> 7, w = mp & 127;
        int ri2 = k >> 5, kx = 2 * (k & 31) + 1;
        float ang = ((kx * w) & 255) * inv128;
        float v = (ri == 0) ? (ri2 == 0 ? cospif(ang) : -sinpif(ang))
                            : (ri2 == 0 ? sinpif(ang) : cospif(ang));
        g_A4o[t] = __float2bfloat16(v * 0.125f);
    } else if (id < 90112) {                  // A5e [128][64]
        int t = id - 81920, h = t >> 6, r = t & 63;
        int ky = (r < 32) ? 2 * r : 2 * (r - 32);
        float ang = ((ky * h) & 255) * inv128;
        float v = (r < 32) ? cospif(ang) : -sinpif(ang);
        g_A5e[t] = __float2bfloat16(v * 0.0625f);
    } else if (id < 98304) {                  // A5o [128][64]
        int t = id - 90112, h = t >> 6, r = t & 63;
        int ky = (r < 32) ? 2 * r + 1 : 2 * (r - 32) + 1;
        float ang = ((ky * h) & 255) * inv128;
        float v = (r < 32) ? cospif(ang) : -sinpif(ang);
        g_A5o[t] = __float2bfloat16(v * 0.0625f);
    }
}
// prep: MLP weight matrices (complex -> stacked real form)
__global__ void k_prep_w(const float* __restrict__ w1, const float* __restrict__ b1,
                         const float* __restrict__ w2, const float* __restrict__ b2) {
    int id = blockIdx.x * 256 + threadIdx.x;
    if (id < 262144) {                         // B3 [8][128][256]
        int n = id >> 15, r = id & 32767, k = r >> 8, o = r & 255;
        float v;
        if (k < 64)
            v = (o < 128) ? w1[((size_t)n * 64 + k) * 128 + o]
                          : w1[((size_t)(8 + n) * 64 + k) * 128 + (o - 128)];
        else {
            int kk = k - 64;
            v = (o < 128) ? -w1[((size_t)(8 + n) * 64 + kk) * 128 + o]
                          : w1[((size_t)n * 64 + kk) * 128 + (o - 128)];
        }
        g_B3[id] = __float2bfloat16(v);
    } else if (id < 524288) {                  // B4 [8][256][128]
        int t = id - 262144, n = t >> 15, r = t & 32767, k = r >> 7, o = r & 127;
        float v;
        if (k < 128)
            v = (o < 64) ? w2[((size_t)n * 128 + k) * 64 + o]
                         : w2[((size_t)(8 + n) * 128 + k) * 64 + (o - 64)];
        else {
            int kk = k - 128;
            v = (o < 64) ? -w2[((size_t)(8 + n) * 128 + kk) * 64 + o]
                         : w2[((size_t)n * 128 + kk) * 64 + (o - 64)];
        }
        g_B4[t] = __float2bfloat16(v);
    } else if (id < 526336) {                  // b3f [8][256]
        int t = id - 524288, n = t >> 8, o = t & 255;
        g_b3f[t] = (o < 128) ? b1[n * 128 + o] : b1[1024 + n * 128 + (o - 128)];
    } else if (id < 527360) {                  // b4f [8][128]
        int t = id - 526336, n = t >> 7, o = t & 127;
        g_b4f[t] = (o < 64) ? b2[n * 64 + o] : b2[512 + n * 64 + (o - 64)];
    }
}

// ---------------------------------------------------------------------------
// S1 (folded): rows m'<64 even ky (vs s=x_h+x_{h+128}); m'>=64 odd (vs d)
__global__ __launch_bounds__(256, 2) void k_s1(const float* __restrict__ x) {
    __shared__ __nv_bfloat16 As[128][72];
    __shared__ __nv_bfloat16 Bss[64][72];
    __shared__ __nv_bfloat16 Bsd[64][72];
    const int tid = threadIdx.x, lane = tid & 31;
    const int wm = (tid >> 5) >> 1, wn = (tid >> 5) & 1;
    float acc[2][4][4] = {};
    uint4 pa[4];
    float4 p1[4], p2[4];
    const int col0 = blockIdx.x * 64, b = blockIdx.y;
    const float* xb = x + (size_t)b * HDIM * N1 + col0;
    pref_a(g_A1f, 128, tid, pa);
    pref_bf(xb, N1, tid, p1);
    pref_bf(xb + (size_t)128 * N1, N1, tid, p2);
#pragma unroll
    for (int kt = 0; kt < 2; kt++) {
        if (kt) __syncthreads();
        store_a(As, tid, pa);
        store_sd(Bss, Bsd, tid, p1, p2);
        __syncthreads();
        if (kt == 0) {
            pref_a(g_A1f + 64, 128, tid, pa);
            pref_bf(xb + (size_t)64 * N1, N1, tid, p1);
            pref_bf(xb + (size_t)192 * N1, N1, tid, p2);
        }
        compute_tile(As, (wm < 2) ? Bss : Bsd, acc, lane, wm, wn);
    }
#pragma unroll
    for (int fm = 0; fm < 2; fm++)
#pragma unroll
        for (int fn = 0; fn < 4; fn++) {
            int col = col0 + wn * 32 + fn * 8 + ((lane & 3) << 1);
            const float* d = acc[fm][fn];
#pragma unroll
            for (int hh = 0; hh < 2; hh++) {
                int mp = wm * 32 + fm * 16 + (lane >> 2) + hh * 8;
                int par = mp >> 6, ri = (mp >> 5) & 1, ky = 2 * (mp & 31) + par;
                size_t idx = ((size_t)(b * 128 + ri * 64 + ky)) * N1 + col;
                *(unsigned*)&g_Y[idx] = pack_bf16(d[hh * 2], d[hh * 2 + 1]);
            }
        }
}

// S2 (folded): per slab (b,ky): even-kx rows vs s=Y[w]+Y[w+128]; odd vs d
__global__ __launch_bounds__(256, 2) void k_s2() {
    __shared__ __nv_bfloat16 As[128][72];
    __shared__ __nv_bfloat16 Bss[64][72];
    __shared__ __nv_bfloat16 Bsd[64][72];
    const int tid = threadIdx.x, lane = tid & 31;
    const int wm = (tid >> 5) >> 1, wn = (tid >> 5) & 1;
    float acc[2][4][4] = {};
    uint4 pa[4], pb[4];
    const int bx = blockIdx.x, slab = blockIdx.y;
    const int b = slab >> 6, ky = slab & 63;
    const int c0 = bx * 64;
    const __nv_bfloat16* yb = g_Y + (size_t)(b * 128 + ky) * N1 + c0;
    pref_a(g_A2f, 256, tid, pa);
    pref_pair(yb, 512, (size_t)128 * 512, tid, pb);
#pragma unroll
    for (int kt = 0; kt < 4; kt++) {
        if (kt) __syncthreads();
        store_a(As, tid, pa);
        store_sd_b(Bss, Bsd, tid, pb);
        __syncthreads();
        if (kt < 3) {
            int k1 = kt + 1;
            int ri = k1 >> 1, w0 = (k1 & 1) * 64;
            pref_a(g_A2f + k1 * 64, 256, tid, pa);
            pref_pair(yb + (size_t)(ri * 64) * N1 + (size_t)w0 * 512, 512,
                      (size_t)128 * 512, tid, pb);
        }
        compute_tile(As, (wm < 2) ? Bss : Bsd, acc, lane, wm, wn);
    }
    size_t pbase = (size_t)slab * 64;
#pragma unroll
    for (int fm = 0; fm < 2; fm++)
#pragma unroll
        for (int fn = 0; fn < 4; fn++) {
            int col = wn * 32 + fn * 8 + ((lane & 3) << 1);
            const float* d = acc[fm][fn];
#pragma unroll
            for (int hh = 0; hh < 2; hh++) {
                int mp = wm * 32 + fm * 16 + (lane >> 2) + hh * 8;
                int par = mp >> 6, rio = (mp >> 5) & 1, kx = 2 * (mp & 31) + par;
                size_t idx = (pbase + kx) * 1024 + (size_t)bx * 128 + rio * 64 + col;
                *(unsigned*)&g_Z[idx] = pack_bf16(d[hh * 2], d[hh * 2 + 1]);
            }
        }
}

// ---------------------------------------------------------------------------
// k_mid: fused S3a+S3b+S4. One CTA = 128 p-rows (2 ky-slabs) x one n-block.
// SMEM rows [1152][72]: Z panels @0 (2x128), H panels @256 (4x128),
// O panels @768 (2 slabs x 2 parities x 64), As/BB @1024 (128).
__global__ __launch_bounds__(256, 1) void k_mid() {
    extern __shared__ __nv_bfloat16 S_[][72];
    __nv_bfloat16 (*S)[72] = S_;
    const int tid = threadIdx.x, lane = tid & 31;
    const int wm = (tid >> 5) >> 1, wn = (tid >> 5) & 1;
    const int bx = blockIdx.x, n = blockIdx.y;
    const int p0 = bx * 128;

    // load Z panels (A operand, K=128) + first B3 tile
    cp_a(g_Z + (size_t)p0 * 1024 + n * 128, 1024, S, tid);
    cp_a(g_Z + (size_t)p0 * 1024 + n * 128 + 64, 1024, S + 128, tid);
    cp_b(g_B3 + (size_t)(n * 128) * 256, 256, S + 1024, tid);
    cp_commit();

    // ---- phase 1: H_j = gelu(Z @ B3[:, j*64..] + b3), STS to H panels ----
#pragma unroll
    for (int j = 0; j < 4; j++) {
        float acc[2][4][4] = {};
#pragma unroll
        for (int t = 0; t < 2; t++) {
            int s = j * 2 + t;
            cp_wait0();
            __syncthreads();
            if (s < 7) {
                int s1 = s + 1, j1 = s1 >> 1, t1 = s1 & 1;
                cp_b(g_B3 + ((size_t)(n * 128 + t1 * 64)) * 256 + j1 * 64, 256,
                     S + 1024 + (s1 & 1) * 64, tid);
                cp_commit();
            }
            compute_tile(S + t * 128, S + 1024 + (s & 1) * 64, acc, lane, wm, wn);
        }
#pragma unroll
        for (int fm = 0; fm < 2; fm++)
#pragma unroll
            for (int fn = 0; fn < 4; fn++) {
                int m = wm * 32 + fm * 16 + (lane >> 2);
                int cL = wn * 32 + fn * 8 + ((lane & 3) << 1);
                float2 bv = *(const float2*)&g_b3f[n * 256 + j * 64 + cL];
                const float* d = acc[fm][fn];
#pragma unroll
                for (int hh = 0; hh < 2; hh++) {
                    *(unsigned*)&S[256 + j * 128 + m + hh * 8][cL] =
                        pack_bf16(gelu_f(d[hh * 2] + bv.x),
                                  gelu_f(d[hh * 2 + 1] + bv.y));
                }
            }
    }

    // ---- phase 2: O = H @ B4 + b4, STS into parity-gathered O panels ----
    __syncthreads();   // H visible; BB free
    cp_b(g_B4 + (size_t)(n * 256) * 128, 128, S + 1024, tid);
    cp_commit();
#pragma unroll
    for (int i = 0; i < 2; i++) {
        float acc[2][4][4] = {};
#pragma unroll
        for (int t = 0; t < 4; t++) {
            int s = i * 4 + t;
            cp_wait0();
            __syncthreads();
            if (s < 7) {
                int s1 = s + 1, i1 = s1 >> 2, t1 = s1 & 3;
                cp_b(g_B4 + ((size_t)(n * 256 + t1 * 64)) * 128 + i1 * 64, 128,
                     S + 1024 + (s1 & 1) * 64, tid);
                cp_commit();
            }
            compute_tile(S + 256 + t * 128, S + 1024 + (s & 1) * 64, acc, lane, wm, wn);
        }
        // epilogue O: ri = i; row = (kx>>1) + 32*i, panel (slab, kx&1)
#pragma unroll
        for (int fm = 0; fm < 2; fm++)
#pragma unroll
            for (int fn = 0; fn < 4; fn++) {
                int m = wm * 32 + fm * 16 + (lane >> 2);
                int cL = wn * 32 + fn * 8 + ((lane & 3) << 1);
                float2 bv = *(const float2*)&g_b4f[n * 128 + i * 64 + cL];
                const float* d = acc[fm][fn];
#pragma unroll
                for (int hh = 0; hh < 2; hh++) {
                    int mm = m + hh * 8;
                    int sl = mm >> 6, kx = mm & 63;
                    int prow = 768 + (sl * 2 + (kx & 1)) * 64 + (kx >> 1) + 32 * i;
                    *(unsigned*)&S[prow][cL] =
                        pack_bf16(d[hh * 2] + bv.x, d[hh * 2 + 1] + bv.y);
                }
            }
    }

    // ---- phase 3: folded inverse-w on SMEM O panels -> U ----
    uint4 pa[4];
#pragma unroll
    for (int m0 = 0; m0 < 256; m0 += 128) {
        pref_a(g_A4e + (size_t)m0 * 64, 64, tid, pa);
        __syncthreads();                 // O visible / prior As users done
        store_a(S + 1024, tid, pa);
        __syncthreads();
        float accP0[2][4][4] = {}, accP1[2][4][4] = {};
        compute_tile(S + 1024, S + 768, accP0, lane, wm, wn);        // slab0 even
        compute_tile(S + 1024, S + 768 + 128, accP1, lane, wm, wn);  // slab1 even
        pref_a(g_A4o + (size_t)m0 * 64, 64, tid, pa);
        __syncthreads();
        store_a(S + 1024, tid, pa);
        __syncthreads();
#pragma unroll
        for (int sl = 0; sl < 2; sl++) {
            float accQ[2][4][4] = {};
            compute_tile(S + 1024, S + 768 + 64 + sl * 128, accQ, lane, wm, wn);
            const int slabG = bx * 2 + sl;
            const int b = slabG >> 6, ky = slabG & 63;
#pragma unroll
            for (int fm = 0; fm < 2; fm++)
#pragma unroll
                for (int fn = 0; fn < 4; fn++) {
                    int cL = wn * 32 + fn * 8 + ((lane & 3) << 1);
                    const float* dP = (sl == 0) ? accP0[fm][fn] : accP1[fm][fn];
                    const float* dQ = accQ[fm][fn];
#pragma unroll
                    for (int hh = 0; hh < 2; hh++) {
                        int mg = m0 + wm * 32 + fm * 16 + (lane >> 2) + hh * 8;
                        int ri = mg >> 7, w = mg & 127;
                        size_t row = (size_t)b * 128 + ri * 64 + ky;
                        size_t i1 = row * N1 + (size_t)w * 512 + n * 64 + cL;
                        size_t i2 = i1 + (size_t)128 * 512;
                        float P0 = dP[hh * 2], P1 = dP[hh * 2 + 1];
                        float Q0 = dQ[hh * 2], Q1 = dQ[hh * 2 + 1];
                        *(unsigned*)&g_U[i1] = pack_bf16(P0 + Q0, P1 + Q1);
                        *(unsigned*)&g_U[i2] = pack_bf16(P0 - Q0, P1 - Q1);
                    }
                }
        }
    }
}

// S5 (folded output): P = even-ky sum, Q = odd-ky sum over U rows;
//   out[h] = x + P + Q ; out[h+128] = x + P - Q
__global__ __launch_bounds__(256, 2) void k_s5(const float* __restrict__ x,
                                               float* __restrict__ out) {
    __shared__ __nv_bfloat16 As[128][72];
    __shared__ __nv_bfloat16 Bs[2][64][72];
    const int tid = threadIdx.x, lane = tid & 31;
    const int wm = (tid >> 5) >> 1, wn = (tid >> 5) & 1;
    float accP[2][4][4] = {};
    float accQ[2][4][4] = {};
    uint4 pa[4];
    const int col0 = blockIdx.x * 64, b = blockIdx.y;
    const __nv_bfloat16* ubase = g_U + (size_t)(b * 128) * N1 + col0;
    pref_a(g_A5e, 64, tid, pa);
    cp_b_gather(ubase, N1, 0, Bs[0], tid);
    cp_commit();
    store_a(As, tid, pa);
    cp_wait0();
    __syncthreads();
    cp_b_gather(ubase, N1, 1, Bs[1], tid);
    cp_commit();
    compute_tile(As, Bs[0], accP, lane, wm, wn);
    __syncthreads();
    pref_a(g_A5o, 64, tid, pa);
    store_a(As, tid, pa);
    cp_wait0();
    __syncthreads();
    compute_tile(As, Bs[1], accQ, lane, wm, wn);
#pragma unroll
    for (int fm = 0; fm < 2; fm++)
#pragma unroll
        for (int fn = 0; fn < 4; fn++) {
            int col = col0 + wn * 32 + fn * 8 + ((lane & 3) << 1);
            const float* dP = accP[fm][fn];
            const float* dQ = accQ[fm][fn];
#pragma unroll
            for (int hh = 0; hh < 2; hh++) {
                int h = wm * 32 + fm * 16 + (lane >> 2) + hh * 8;
                float P0 = dP[hh * 2], P1 = dP[hh * 2 + 1];
                float Q0 = dQ[hh * 2], Q1 = dQ[hh * 2 + 1];
                size_t i1 = ((size_t)b * HDIM + h) * N1 + col;
                size_t i2 = ((size_t)b * HDIM + h + 128) * N1 + col;
                float2 x1 = *(const float2*)&x[i1];
                float2 x2 = *(const float2*)&x[i2];
                float2 o1, o2;
                o1.x = x1.x + P0 + Q0; o1.y = x1.y + P1 + Q1;
                o2.x = x2.x + P0 - Q0; o2.y = x2.y + P1 - Q1;
                *(float2*)&out[i1] = o1;
                *(float2*)&out[i2] = o2;
            }
        }
}

// ---------------------------------------------------------------------------
extern "C" void kernel_launch(void* const* d_in, const int* in_sizes, int n_in,
                              void* d_out, int out_size) {
    const float* x  = (const float*)d_in[0];
    const float* w1 = (const float*)d_in[1];
    const float* b1 = (const float*)d_in[2];
    const float* w2 = (const float*)d_in[3];
    const float* b2 = (const float*)d_in[4];
    float* out = (float*)d_out;

    cudaFuncSetAttribute(k_mid, cudaFuncAttributeMaxDynamicSharedMemorySize, SMEM_MID);

    k_prep_dft<<<384, 256>>>();
    k_prep_w<<<2060, 256>>>(w1, b1, w2, b2);
    k_s1<<<dim3(N1 / 64, BATCH), 256>>>(x);
    k_s2<<<dim3(8, BATCH * KM), 256>>>();
    k_mid<<<dim3(64, NBLK), 256, SMEM_MID>>>();
    k_s5<<<dim3(N1 / 64, BATCH), 256>>>(x, out);
}

// round 17
// speedup vs baseline: 1.0387x; 1.0387x over previous
#include <cuda_runtime.h>
#include <cuda_bf16.h>
#include <math.h>

#define BATCH 2
#define HDIM 256
#define WDIM 256
#define CDIM 512
#define KM 64
#define NBLK 8
#define N1 131072          /* WDIM*CDIM */
#define SMEM_S2 ((8 * 64 + 2 * 128) * 72 * 2)   /* 110592 B dynamic smem */

// ---------------- scratch (device globals; uint4 for 16B alignment) --------
__device__ uint4 g_A1f_4[128 * 128 / 8];            // folded h-DFT
__device__ uint4 g_A2f4_4[2 * 128 * 64 / 8];        // radix-4 w-DFT [kt][mp][w]
__device__ uint4 g_A4e_4[256 * 64 / 8];             // folded inv-w, even kx
__device__ uint4 g_A4o_4[256 * 64 / 8];             // folded inv-w, odd kx
__device__ uint4 g_A5e_4[128 * 64 / 8];             // folded inv-h, even ky
__device__ uint4 g_A5o_4[128 * 64 / 8];             // folded inv-h, odd ky
__device__ uint4 g_B3_4[8 * 128 * 256 / 8];
__device__ uint4 g_B4_4[8 * 256 * 128 / 8];
__device__ float g_b3f[8 * 256];
__device__ float g_b4f[8 * 128];
__device__ uint4 g_Y_4[(size_t)2 * 128 * N1 / 8];   // [b][ri*64+ky][w*512+c]
__device__ uint4 g_Z_4[(size_t)8192 * 1024 / 8];    // [p][n*128 + ri*64 + c64]
__device__ uint4 g_H_4[(size_t)8192 * 2048 / 8];    // [p][n*256 + o2]
__device__ uint4 g_O_4[(size_t)16384 * 512 / 8];    // [((b64ky)*2+ri)*64+kx][c]
__device__ uint4 g_U_4[(size_t)2 * 128 * N1 / 8];   // [b][ri*64+ky][w*512+c]

#define g_A1f  ((__nv_bfloat16*)g_A1f_4)
#define g_A2f4 ((__nv_bfloat16*)g_A2f4_4)
#define g_A4e  ((__nv_bfloat16*)g_A4e_4)
#define g_A4o  ((__nv_bfloat16*)g_A4o_4)
#define g_A5e  ((__nv_bfloat16*)g_A5e_4)
#define g_A5o  ((__nv_bfloat16*)g_A5o_4)
#define g_B3   ((__nv_bfloat16*)g_B3_4)
#define g_B4   ((__nv_bfloat16*)g_B4_4)
#define g_Y    ((__nv_bfloat16*)g_Y_4)
#define g_Z    ((__nv_bfloat16*)g_Z_4)
#define g_H    ((__nv_bfloat16*)g_H_4)
#define g_O    ((__nv_bfloat16*)g_O_4)
#define g_U    ((__nv_bfloat16*)g_U_4)

// ---------------------------------------------------------------------------
__device__ __forceinline__ float gelu_f(float v) {
    return 0.5f * v * (1.0f + erff(v * 0.70710678118654752440f));
}
__device__ __forceinline__ unsigned pack_bf16(float a, float b) {
    unsigned lo = __bfloat16_as_ushort(__float2bfloat16(a));
    unsigned hi = __bfloat16_as_ushort(__float2bfloat16(b));
    return lo | (hi << 16);
}
__device__ __forceinline__ void unpack8(uint4 u, float* f) {
    const __nv_bfloat162* p = (const __nv_bfloat162*)&u;
#pragma unroll
    for (int i = 0; i < 4; i++) {
        float2 t = __bfloat1622float2(p[i]);
        f[2 * i] = t.x; f[2 * i + 1] = t.y;
    }
}
__device__ __forceinline__ uint4 pack8(const float* f) {
    uint4 u;
    unsigned* w = (unsigned*)&u;
#pragma unroll
    for (int i = 0; i < 4; i++) w[i] = pack_bf16(f[2 * i], f[2 * i + 1]);
    return u;
}
__device__ __forceinline__ void mma16816(float* d, const unsigned* a, const unsigned* b) {
    asm volatile(
        "mma.sync.aligned.m16n8k16.row.col.f32.bf16.bf16.f32 "
        "{%0,%1,%2,%3}, {%4,%5,%6,%7}, {%8,%9}, {%0,%1,%2,%3};\n"
        : "+f"(d[0]), "+f"(d[1]), "+f"(d[2]), "+f"(d[3])
        : "r"(a[0]), "r"(a[1]), "r"(a[2]), "r"(a[3]), "r"(b[0]), "r"(b[1]));
}

// ---- cp.async helpers -----------------------------------------------------
__device__ __forceinline__ void cpa16(void* sm, const void* g) {
    unsigned s = (unsigned)__cvta_generic_to_shared(sm);
    asm volatile("cp.async.cg.shared.global [%0], [%1], 16;\n" :: "r"(s), "l"(g));
}
__device__ __forceinline__ void cp_commit() {
    asm volatile("cp.async.commit_group;\n" ::: "memory");
}
__device__ __forceinline__ void cp_wait0() {
    asm volatile("cp.async.wait_group 0;\n" ::: "memory");
}

// ---- tile movers ----------------------------------------------------------
__device__ __forceinline__ void pref_a(const __nv_bfloat16* __restrict__ src,
                                       size_t stride, int tid, uint4* pa) {
    int r = tid >> 1, c0 = (tid & 1) << 5;
    const uint4* p = (const uint4*)(src + (size_t)r * stride + c0);
    pa[0] = p[0]; pa[1] = p[1]; pa[2] = p[2]; pa[3] = p[3];
}
__device__ __forceinline__ void store_a(__nv_bfloat16 (*As)[72], int tid, const uint4* pa) {
    int r = tid >> 1, c0 = (tid & 1) << 5;
    uint4* d = (uint4*)&As[r][c0];
    d[0] = pa[0]; d[1] = pa[1]; d[2] = pa[2]; d[3] = pa[3];
}
__device__ __forceinline__ void cp_a(const __nv_bfloat16* __restrict__ src,
                                     size_t stride, __nv_bfloat16 (*As)[72], int tid) {
    int r = tid >> 1, c0 = (tid & 1) << 5;
    const __nv_bfloat16* g = src + (size_t)r * stride + c0;
#pragma unroll
    for (int j = 0; j < 4; j++) cpa16(&As[r][c0 + j * 8], g + j * 8);
}
__device__ __forceinline__ void pref_b(const __nv_bfloat16* __restrict__ src,
                                       size_t stride, int tid, uint4* pb) {
    int r = tid >> 2, c0 = (tid & 3) << 4;
    const uint4* p = (const uint4*)(src + (size_t)r * stride + c0);
    pb[0] = p[0]; pb[1] = p[1];
}
__device__ __forceinline__ void store_b(__nv_bfloat16 (*Bs)[72], int tid, const uint4* pb) {
    int r = tid >> 2, c0 = (tid & 3) << 4;
    uint4* d = (uint4*)&Bs[r][c0];
    d[0] = pb[0]; d[1] = pb[1];
}
__device__ __forceinline__ void cp_b(const __nv_bfloat16* __restrict__ src,
                                     size_t stride, __nv_bfloat16 (*Bs)[72], int tid) {
    int r = tid >> 2, c0 = (tid & 3) << 4;
    const __nv_bfloat16* g = src + (size_t)r * stride + c0;
    cpa16(&Bs[r][c0], g);
    cpa16(&Bs[r][c0 + 8], g + 8);
}
// gather-rows cp (even/odd interleave), generic stride
__device__ __forceinline__ void cp_b_gather(const __nv_bfloat16* __restrict__ base,
                                            size_t stride, int koff,
                                            __nv_bfloat16 (*Bs)[72], int tid) {
    int r = tid >> 2, c0 = (tid & 3) << 4;
    int row = (r < 32) ? (2 * r + koff) : (64 + 2 * (r - 32) + koff);
    const __nv_bfloat16* g = base + (size_t)row * stride + c0;
    cpa16(&Bs[r][c0], g);
    cpa16(&Bs[r][c0 + 8], g + 8);
}
// f32 source prefetch (16 floats/thread)
__device__ __forceinline__ void pref_bf(const float* __restrict__ src,
                                        size_t stride, int tid, float4* pf) {
    int r = tid >> 2, c0 = (tid & 3) << 4;
    const float4* p = (const float4*)(src + (size_t)r * stride + c0);
    pf[0] = p[0]; pf[1] = p[1]; pf[2] = p[2]; pf[3] = p[3];
}
__device__ __forceinline__ void store_sd(__nv_bfloat16 (*Bss)[72], __nv_bfloat16 (*Bsd)[72],
                                         int tid, const float4* p1, const float4* p2) {
    int r = tid >> 2, c0 = (tid & 3) << 4;
#pragma unroll
    for (int h = 0; h < 2; h++) {
        float4 a0 = p1[h * 2], a1 = p1[h * 2 + 1];
        float4 b0 = p2[h * 2], b1 = p2[h * 2 + 1];
        uint4 s, d;
        s.x = pack_bf16(a0.x + b0.x, a0.y + b0.y);
        s.y = pack_bf16(a0.z + b0.z, a0.w + b0.w);
        s.z = pack_bf16(a1.x + b1.x, a1.y + b1.y);
        s.w = pack_bf16(a1.z + b1.z, a1.w + b1.w);
        d.x = pack_bf16(a0.x - b0.x, a0.y - b0.y);
        d.y = pack_bf16(a0.z - b0.z, a0.w - b0.w);
        d.z = pack_bf16(a1.x - b1.x, a1.y - b1.y);
        d.w = pack_bf16(a1.z - b1.z, a1.w - b1.w);
        *(uint4*)&Bss[r][c0 + h * 8] = s;
        *(uint4*)&Bsd[r][c0 + h * 8] = d;
    }
}
// core: one 64-deep K tile, block 128x64, 8 warps of 32x32, ldmatrix path
__device__ __forceinline__ void compute_tile(const __nv_bfloat16 (*As)[72],
                                             const __nv_bfloat16 (*Bs)[72],
                                             float acc[2][4][4], int lane, int wm, int wn) {
    const int r8 = lane & 7, q = lane >> 3;
#pragma unroll
    for (int kk = 0; kk < 4; kk++) {
        const int k0 = kk * 16;
        unsigned a[2][4], b[4][2];
#pragma unroll
        for (int fm = 0; fm < 2; fm++) {
            int row = wm * 32 + fm * 16 + (q & 1) * 8 + r8;
            int col = k0 + (q >> 1) * 8;
            unsigned addr = (unsigned)__cvta_generic_to_shared(&As[row][col]);
            asm volatile("ldmatrix.sync.aligned.m8n8.x4.shared.b16 {%0,%1,%2,%3}, [%4];\n"
                         : "=r"(a[fm][0]), "=r"(a[fm][1]), "=r"(a[fm][2]), "=r"(a[fm][3])
                         : "r"(addr));
        }
#pragma unroll
        for (int fn2 = 0; fn2 < 2; fn2++) {
            int krow = k0 + (q & 1) * 8 + r8;
            int ncol = wn * 32 + fn2 * 16 + (q >> 1) * 8;
            unsigned addr = (unsigned)__cvta_generic_to_shared(&Bs[krow][ncol]);
            asm volatile("ldmatrix.sync.aligned.m8n8.x4.trans.shared.b16 {%0,%1,%2,%3}, [%4];\n"
                         : "=r"(b[fn2 * 2][0]), "=r"(b[fn2 * 2][1]),
                           "=r"(b[fn2 * 2 + 1][0]), "=r"(b[fn2 * 2 + 1][1])
                         : "r"(addr));
        }
#pragma unroll
        for (int fm = 0; fm < 2; fm++)
#pragma unroll
            for (int fn = 0; fn < 4; fn++) mma16816(acc[fm][fn], a[fm], b[fn]);
    }
}

// ---------------------------------------------------------------------------
// prep: folded DFT A-matrices
__global__ void k_prep_dft() {
    int id = blockIdx.x * 256 + threadIdx.x;
    const float inv128 = 1.0f / 128.0f;
    if (id < 16384) {                         // A1f [128][128]
        int mp = id >> 7, h = id & 127;
        int par = mp >> 6, ri = (mp >> 5) & 1, ky = 2 * (mp & 31) + par;
        float t = ((ky * h) & 255) * inv128;
        float v = ri ? -sinpif(t) : cospif(t);
        g_A1f[id] = __float2bfloat16(v * 0.0625f);
    } else if (id < 32768) {                  // A2f4 [2][128][64]
        int t = id - 16384;
        int kt = t >> 13, mp = (t >> 6) & 127, w = t & 63;
        int c = mp >> 5, rio = (mp >> 4) & 1, j = mp & 15;
        int kx = 4 * j + c;
        float ang = ((kx * w) & 255) * inv128;
        float v;
        if (kt == 0) v = rio ? -sinpif(ang) : cospif(ang);
        else         v = rio ?  cospif(ang) : sinpif(ang);
        g_A2f4[t] = __float2bfloat16(v * 0.0625f);
    } else if (id < 49152) {                  // A4e [256][64]
        int t = id - 32768, mp = t >> 6, k = t & 63;
        int ri = mp >> 7, w = mp & 127;
        int ri2 = k >> 5, kx = 2 * (k & 31);
        float sc = (kx == 0) ? 0.0625f : 0.125f;
        float ang = ((kx * w) & 255) * inv128;
        float v = (ri == 0) ? (ri2 == 0 ? cospif(ang) : -sinpif(ang))
                            : (ri2 == 0 ? sinpif(ang) : cospif(ang));
        g_A4e[t] = __float2bfloat16(v * sc);
    } else if (id < 65536) {                  // A4o [256][64]
        int t = id - 49152, mp = t >> 6, k = t & 63;
        int ri = mp >> 7, w = mp & 127;
        int ri2 = k >> 5, kx = 2 * (k & 31) + 1;
        float ang = ((kx * w) & 255) * inv128;
        float v = (ri == 0) ? (ri2 == 0 ? cospif(ang) : -sinpif(ang))
                            : (ri2 == 0 ? sinpif(ang) : cospif(ang));
        g_A4o[t] = __float2bfloat16(v * 0.125f);
    } else if (id < 73728) {                  // A5e [128][64]
        int t = id - 65536, h = t >> 6, r = t & 63;
        int ky = (r < 32) ? 2 * r : 2 * (r - 32);
        float ang = ((ky * h) & 255) * inv128;
        float v = (r < 32) ? cospif(ang) : -sinpif(ang);
        g_A5e[t] = __float2bfloat16(v * 0.0625f);
    } else if (id < 81920) {                  // A5o [128][64]
        int t = id - 73728, h = t >> 6, r = t & 63;
        int ky = (r < 32) ? 2 * r + 1 : 2 * (r - 32) + 1;
        float ang = ((ky * h) & 255) * inv128;
        float v = (r < 32) ? cospif(ang) : -sinpif(ang);
        g_A5o[t] = __float2bfloat16(v * 0.0625f);
    }
}
// prep: MLP weight matrices (complex -> stacked real form)
__global__ void k_prep_w(const float* __restrict__ w1, const float* __restrict__ b1,
                         const float* __restrict__ w2, const float* __restrict__ b2) {
    int id = blockIdx.x * 256 + threadIdx.x;
    if (id < 262144) {                         // B3 [8][128][256]
        int n = id >> 15, r = id & 32767, k = r >> 8, o = r & 255;
        float v;
        if (k < 64)
            v = (o < 128) ? w1[((size_t)n * 64 + k) * 128 + o]
                          : w1[((size_t)(8 + n) * 64 + k) * 128 + (o - 128)];
        else {
            int kk = k - 64;
            v = (o < 128) ? -w1[((size_t)(8 + n) * 64 + kk) * 128 + o]
                          : w1[((size_t)n * 64 + kk) * 128 + (o - 128)];
        }
        g_B3[id] = __float2bfloat16(v);
    } else if (id < 524288) {                  // B4 [8][256][128]
        int t = id - 262144, n = t >> 15, r = t & 32767, k = r >> 7, o = r & 127;
        float v;
        if (k < 128)
            v = (o < 64) ? w2[((size_t)n * 128 + k) * 64 + o]
                         : w2[((size_t)(8 + n) * 128 + k) * 64 + (o - 64)];
        else {
            int kk = k - 128;
            v = (o < 64) ? -w2[((size_t)(8 + n) * 128 + kk) * 64 + o]
                         : w2[((size_t)n * 128 + kk) * 64 + (o - 64)];
        }
        g_B4[t] = __float2bfloat16(v);
    } else if (id < 526336) {                  // b3f [8][256]
        int t = id - 524288, n = t >> 8, o = t & 255;
        g_b3f[t] = (o < 128) ? b1[n * 128 + o] : b1[1024 + n * 128 + (o - 128)];
    } else if (id < 527360) {                  // b4f [8][128]
        int t = id - 526336, n = t >> 7, o = t & 127;
        g_b4f[t] = (o < 64) ? b2[n * 64 + o] : b2[512 + n * 64 + (o - 64)];
    }
}

// ---------------------------------------------------------------------------
// S1 (folded): rows m'<64 even ky (vs s=x_h+x_{h+128}); m'>=64 odd (vs d)
__global__ __launch_bounds__(256, 2) void k_s1(const float* __restrict__ x) {
    __shared__ __nv_bfloat16 As[128][72];
    __shared__ __nv_bfloat16 Bss[64][72];
    __shared__ __nv_bfloat16 Bsd[64][72];
    const int tid = threadIdx.x, lane = tid & 31;
    const int wm = (tid >> 5) >> 1, wn = (tid >> 5) & 1;
    float acc[2][4][4] = {};
    uint4 pa[4];
    float4 p1[4], p2[4];
    const int col0 = blockIdx.x * 64, b = blockIdx.y;
    const float* xb = x + (size_t)b * HDIM * N1 + col0;
    pref_a(g_A1f, 128, tid, pa);
    pref_bf(xb, N1, tid, p1);
    pref_bf(xb + (size_t)128 * N1, N1, tid, p2);
#pragma unroll
    for (int kt = 0; kt < 2; kt++) {
        if (kt) __syncthreads();
        store_a(As, tid, pa);
        store_sd(Bss, Bsd, tid, p1, p2);
        __syncthreads();
        if (kt == 0) {
            pref_a(g_A1f + 64, 128, tid, pa);
            pref_bf(xb + (size_t)64 * N1, N1, tid, p1);
            pref_bf(xb + (size_t)192 * N1, N1, tid, p2);
        }
        compute_tile(As, (wm < 2) ? Bss : Bsd, acc, lane, wm, wn);
    }
#pragma unroll
    for (int fm = 0; fm < 2; fm++)
#pragma unroll
        for (int fn = 0; fn < 4; fn++) {
            int col = col0 + wn * 32 + fn * 8 + ((lane & 3) << 1);
            const float* d = acc[fm][fn];
#pragma unroll
            for (int hh = 0; hh < 2; hh++) {
                int mp = wm * 32 + fm * 16 + (lane >> 2) + hh * 8;
                int par = mp >> 6, ri = (mp >> 5) & 1, ky = 2 * (mp & 31) + par;
                size_t idx = ((size_t)(b * 128 + ri * 64 + ky)) * N1 + col;
                *(unsigned*)&g_Y[idx] = pack_bf16(d[hh * 2], d[hh * 2 + 1]);
            }
        }
}

// S2 (radix-4): per slab (b,ky), classes kx mod 4 per warp-row-group.
// Combos: T0=Sr+Sr' T1=Si+Si' T2=Dr+Di' T3=Di-Dr' T4=Sr-Sr' T5=Si-Si'
//         T6=Dr-Di' T7=Di+Dr'   (S/D from w vs w+128; primes at w+64)
// class c uses (T[2c], T[2c+1]); A2f4 kt0 over Qr, kt1 over Qi.
__global__ __launch_bounds__(256, 2) void k_s2() {
    extern __shared__ __nv_bfloat16 S_[][72];
    __nv_bfloat16 (*S)[72] = S_;        // T_t at t*64; As0 @512; As1 @640
    const int tid = threadIdx.x, lane = tid & 31;
    const int wm = (tid >> 5) >> 1, wn = (tid >> 5) & 1;
    const int bx = blockIdx.x, slab = blockIdx.y;
    const int b = slab >> 6, ky = slab & 63;
    cp_a(g_A2f4, 64, S + 512, tid);
    cp_a(g_A2f4 + 8192, 64, S + 640, tid);
    cp_commit();
    const __nv_bfloat16* base_r = g_Y + (size_t)(b * 128 + ky) * N1 + bx * 64;
    const __nv_bfloat16* base_i = base_r + (size_t)64 * N1;
    const int r = tid >> 2, cq = (tid & 3) << 4;
#pragma unroll
    for (int h = 0; h < 2; h++) {
        const int co = cq + h * 8;
        uint4 qa[4];
        float f[4][8];
        // Yr quarters
#pragma unroll
        for (int q = 0; q < 4; q++)
            qa[q] = *(const uint4*)(base_r + (size_t)(q * 64 + r) * 512 + co);
#pragma unroll
        for (int q = 0; q < 4; q++) unpack8(qa[q], f[q]);
        float t0[8], t4[8], dr8[8], drp8[8];
#pragma unroll
        for (int i = 0; i < 8; i++) {
            float s = f[0][i] + f[2][i], sp = f[1][i] + f[3][i];
            t0[i] = s + sp; t4[i] = s - sp;
            dr8[i] = f[0][i] - f[2][i]; drp8[i] = f[1][i] - f[3][i];
        }
        *(uint4*)&S[0 * 64 + r][co] = pack8(t0);
        *(uint4*)&S[4 * 64 + r][co] = pack8(t4);
        // Yi quarters
#pragma unroll
        for (int q = 0; q < 4; q++)
            qa[q] = *(const uint4*)(base_i + (size_t)(q * 64 + r) * 512 + co);
#pragma unroll
        for (int q = 0; q < 4; q++) unpack8(qa[q], f[q]);
        float t1[8], t5[8], t2[8], t3[8], t6[8], t7[8];
#pragma unroll
        for (int i = 0; i < 8; i++) {
            float s = f[0][i] + f[2][i], sp = f[1][i] + f[3][i];
            t1[i] = s + sp; t5[i] = s - sp;
            float di = f[0][i] - f[2][i], dip = f[1][i] - f[3][i];
            t2[i] = dr8[i] + dip; t6[i] = dr8[i] - dip;
            t3[i] = di - drp8[i]; t7[i] = di + drp8[i];
        }
        *(uint4*)&S[1 * 64 + r][co] = pack8(t1);
        *(uint4*)&S[5 * 64 + r][co] = pack8(t5);
        *(uint4*)&S[2 * 64 + r][co] = pack8(t2);
        *(uint4*)&S[6 * 64 + r][co] = pack8(t6);
        *(uint4*)&S[3 * 64 + r][co] = pack8(t3);
        *(uint4*)&S[7 * 64 + r][co] = pack8(t7);
    }
    cp_wait0();
    __syncthreads();
    float acc[2][4][4] = {};
    compute_tile(S + 512, S + (2 * wm) * 64, acc, lane, wm, wn);
    compute_tile(S + 640, S + (2 * wm + 1) * 64, acc, lane, wm, wn);
    size_t pbase = (size_t)slab * 64;
#pragma unroll
    for (int fm = 0; fm < 2; fm++)
#pragma unroll
        for (int fn = 0; fn < 4; fn++) {
            int col = wn * 32 + fn * 8 + ((lane & 3) << 1);
            const float* d = acc[fm][fn];
#pragma unroll
            for (int hh = 0; hh < 2; hh++) {
                int mp = wm * 32 + fm * 16 + (lane >> 2) + hh * 8;
                int rio = (mp >> 4) & 1, j = mp & 15;
                int kx = 4 * j + wm;
                size_t idx = (pbase + kx) * 1024 + (size_t)bx * 128 + rio * 64 + col;
                *(unsigned*)&g_Z[idx] = pack_bf16(d[hh * 2], d[hh * 2 + 1]);
            }
        }
}

// S3a: H = gelu(Z @ B3 + b3)  (A cp.async double, B reg-prefetch single)
__global__ __launch_bounds__(256) void k_s3a() {
    __shared__ __nv_bfloat16 As[2][128][72];
    __shared__ __nv_bfloat16 Bs[64][72];
    const int tid = threadIdx.x, lane = tid & 31;
    const int wm = (tid >> 5) >> 1, wn = (tid >> 5) & 1;
    float acc[2][4][4] = {};
    uint4 pb[2];
    const int p0 = blockIdx.x * 128, o0 = blockIdx.y * 64, n = blockIdx.z;
    const __nv_bfloat16* abase = g_Z + (size_t)p0 * 1024 + n * 128;
    const __nv_bfloat16* bbase = g_B3 + (size_t)(n * 128) * 256 + o0;
    cp_a(abase, 1024, As[0], tid);
    cp_commit();
    pref_b(bbase, 256, tid, pb);
#pragma unroll
    for (int kt = 0; kt < 2; kt++) {
        cp_wait0();
        __syncthreads();
        store_b(Bs, tid, pb);
        if (kt < 1) {
            cp_a(abase + 64, 1024, As[1], tid);
            cp_commit();
            pref_b(bbase + (size_t)64 * 256, 256, tid, pb);
        }
        __syncthreads();
        compute_tile(As[kt & 1], Bs, acc, lane, wm, wn);
    }
#pragma unroll
    for (int fm = 0; fm < 2; fm++)
#pragma unroll
        for (int fn = 0; fn < 4; fn++) {
            int m = wm * 32 + fm * 16 + (lane >> 2);
            int o2 = o0 + wn * 32 + fn * 8 + ((lane & 3) << 1);
            float2 bv = *(const float2*)&g_b3f[n * 256 + o2];
            const float* d = acc[fm][fn];
#pragma unroll
            for (int hh = 0; hh < 2; hh++) {
                int p = p0 + m + hh * 8;
                size_t idx = (size_t)p * 2048 + n * 256 + o2;
                *(unsigned*)&g_H[idx] =
                    pack_bf16(gelu_f(d[hh * 2] + bv.x), gelu_f(d[hh * 2 + 1] + bv.y));
            }
        }
}

// S3b: O = H @ B4 + b4  (A cp.async double, B reg-prefetch single)
__global__ __launch_bounds__(256) void k_s3b() {
    __shared__ __nv_bfloat16 As[2][128][72];
    __shared__ __nv_bfloat16 Bs[64][72];
    const int tid = threadIdx.x, lane = tid & 31;
    const int wm = (tid >> 5) >> 1, wn = (tid >> 5) & 1;
    float acc[2][4][4] = {};
    uint4 pb[2];
    const int p0 = blockIdx.x * 128, o0 = blockIdx.y * 64, n = blockIdx.z;
    const __nv_bfloat16* abase = g_H + (size_t)p0 * 2048 + n * 256;
    const __nv_bfloat16* bbase = g_B4 + (size_t)(n * 256) * 128 + o0;
    cp_a(abase, 2048, As[0], tid);
    cp_commit();
    pref_b(bbase, 128, tid, pb);
#pragma unroll
    for (int kt = 0; kt < 4; kt++) {
        cp_wait0();
        __syncthreads();
        store_b(Bs, tid, pb);
        if (kt < 3) {
            cp_a(abase + (kt + 1) * 64, 2048, As[(kt + 1) & 1], tid);
            cp_commit();
            pref_b(bbase + (size_t)((kt + 1) * 64) * 128, 128, tid, pb);
        }
        __syncthreads();
        compute_tile(As[kt & 1], Bs, acc, lane, wm, wn);
    }
#pragma unroll
    for (int fm = 0; fm < 2; fm++)
#pragma unroll
        for (int fn = 0; fn < 4; fn++) {
            int m = wm * 32 + fm * 16 + (lane >> 2);
            int o2 = o0 + wn * 32 + fn * 8 + ((lane & 3) << 1);
            float2 bv = *(const float2*)&g_b4f[n * 128 + o2];
            int ri = o2 >> 6, c = n * 64 + (o2 & 63);
            const float* d = acc[fm][fn];
#pragma unroll
            for (int hh = 0; hh < 2; hh++) {
                int p = p0 + m + hh * 8;
                int b = p >> 12, ky = (p >> 6) & 63, kx = p & 63;
                size_t idx = (((size_t)(b * 64 + ky) * 2 + ri) * 64 + kx) * 512 + c;
                *(unsigned*)&g_O[idx] =
                    pack_bf16(d[hh * 2] + bv.x, d[hh * 2 + 1] + bv.y);
            }
        }
}

// S4 (folded output): P = even-kx, Q = odd-kx over O rows;
//   U[ri][w] = P+Q ; U[ri][w+128] = P-Q
__global__ __launch_bounds__(256, 2) void k_s4() {
    __shared__ __nv_bfloat16 As[128][72];
    __shared__ __nv_bfloat16 Bs[2][64][72];
    const int tid = threadIdx.x, lane = tid & 31;
    const int wm = (tid >> 5) >> 1, wn = (tid >> 5) & 1;
    float accP[2][4][4] = {};
    float accQ[2][4][4] = {};
    uint4 pa[4];
    const int c0 = blockIdx.x * 64, m0 = blockIdx.y * 128, slab = blockIdx.z;
    const int b = slab >> 6, ky = slab & 63;
    const __nv_bfloat16* obase = g_O + ((size_t)slab * 128) * 512 + c0;
    pref_a(g_A4e + (size_t)m0 * 64, 64, tid, pa);
    cp_b_gather(obase, 512, 0, Bs[0], tid);
    cp_commit();
    store_a(As, tid, pa);
    cp_wait0();
    __syncthreads();
    cp_b_gather(obase, 512, 1, Bs[1], tid);
    cp_commit();
    compute_tile(As, Bs[0], accP, lane, wm, wn);
    __syncthreads();
    pref_a(g_A4o + (size_t)m0 * 64, 64, tid, pa);
    store_a(As, tid, pa);
    cp_wait0();
    __syncthreads();
    compute_tile(As, Bs[1], accQ, lane, wm, wn);
#pragma unroll
    for (int fm = 0; fm < 2; fm++)
#pragma unroll
        for (int fn = 0; fn < 4; fn++) {
            int c = c0 + wn * 32 + fn * 8 + ((lane & 3) << 1);
            const float* dP = accP[fm][fn];
            const float* dQ = accQ[fm][fn];
#pragma unroll
            for (int hh = 0; hh < 2; hh++) {
                int mp = m0 + wm * 32 + fm * 16 + (lane >> 2) + hh * 8;
                int ri = mp >> 7, w = mp & 127;
                size_t row = (size_t)b * 128 + ri * 64 + ky;
                size_t i1 = row * N1 + (size_t)w * 512 + c;
                size_t i2 = i1 + (size_t)128 * 512;
                float P0 = dP[hh * 2], P1 = dP[hh * 2 + 1];
                float Q0 = dQ[hh * 2], Q1 = dQ[hh * 2 + 1];
                *(unsigned*)&g_U[i1] = pack_bf16(P0 + Q0, P1 + Q1);
                *(unsigned*)&g_U[i2] = pack_bf16(P0 - Q0, P1 - Q1);
            }
        }
}

// S5 (folded output): P = even-ky sum, Q = odd-ky sum over U rows;
//   out[h] = x + P + Q ; out[h+128] = x + P - Q
__global__ __launch_bounds__(256, 2) void k_s5(const float* __restrict__ x,
                                               float* __restrict__ out) {
    __shared__ __nv_bfloat16 As[128][72];
    __shared__ __nv_bfloat16 Bs[2][64][72];
    const int tid = threadIdx.x, lane = tid & 31;
    const int wm = (tid >> 5) >> 1, wn = (tid >> 5) & 1;
    float accP[2][4][4] = {};
    float accQ[2][4][4] = {};
    uint4 pa[4];
    const int col0 = blockIdx.x * 64, b = blockIdx.y;
    const __nv_bfloat16* ubase = g_U + (size_t)(b * 128) * N1 + col0;
    pref_a(g_A5e, 64, tid, pa);
    cp_b_gather(ubase, N1, 0, Bs[0], tid);
    cp_commit();
    store_a(As, tid, pa);
    cp_wait0();
    __syncthreads();
    cp_b_gather(ubase, N1, 1, Bs[1], tid);
    cp_commit();
    compute_tile(As, Bs[0], accP, lane, wm, wn);
    __syncthreads();
    pref_a(g_A5o, 64, tid, pa);
    store_a(As, tid, pa);
    cp_wait0();
    __syncthreads();
    compute_tile(As, Bs[1], accQ, lane, wm, wn);
#pragma unroll
    for (int fm = 0; fm < 2; fm++)
#pragma unroll
        for (int fn = 0; fn < 4; fn++) {
            int col = col0 + wn * 32 + fn * 8 + ((lane & 3) << 1);
            const float* dP = accP[fm][fn];
            const float* dQ = accQ[fm][fn];
#pragma unroll
            for (int hh = 0; hh < 2; hh++) {
                int h = wm * 32 + fm * 16 + (lane >> 2) + hh * 8;
                float P0 = dP[hh * 2], P1 = dP[hh * 2 + 1];
                float Q0 = dQ[hh * 2], Q1 = dQ[hh * 2 + 1];
                size_t i1 = ((size_t)b * HDIM + h) * N1 + col;
                size_t i2 = ((size_t)b * HDIM + h + 128) * N1 + col;
                float2 x1 = *(const float2*)&x[i1];
                float2 x2 = *(const float2*)&x[i2];
                float2 o1, o2;
                o1.x = x1.x + P0 + Q0; o1.y = x1.y + P1 + Q1;
                o2.x = x2.x + P0 - Q0; o2.y = x2.y + P1 - Q1;
                *(float2*)&out[i1] = o1;
                *(float2*)&out[i2] = o2;
            }
        }
}

// ---------------------------------------------------------------------------
extern "C" void kernel_launch(void* const* d_in, const int* in_sizes, int n_in,
                              void* d_out, int out_size) {
    const float* x  = (const float*)d_in[0];
    const float* w1 = (const float*)d_in[1];
    const float* b1 = (const float*)d_in[2];
    const float* w2 = (const float*)d_in[3];
    const float* b2 = (const float*)d_in[4];
    float* out = (float*)d_out;

    cudaFuncSetAttribute(k_s2, cudaFuncAttributeMaxDynamicSharedMemorySize, SMEM_S2);

    k_prep_dft<<<320, 256>>>();
    k_prep_w<<<2060, 256>>>(w1, b1, w2, b2);
    k_s1<<<dim3(N1 / 64, BATCH), 256>>>(x);
    k_s2<<<dim3(8, BATCH * KM), 256, SMEM_S2>>>();
    k_s3a<<<dim3(64, 4, NBLK), 256>>>();
    k_s3b<<<dim3(64, 2, NBLK), 256>>>();
    k_s4<<<dim3(8, 2, BATCH * KM), 256>>>();
    k_s5<<<dim3(N1 / 64, BATCH), 256>>>(x, out);
}